// round 3
// baseline (speedup 1.0000x reference)
#include <cuda_runtime.h>
#include <cuda_bf16.h>
#include <math.h>

// ---------------------------------------------------------------------------
// Seq2Seq LSTM (B=64, S=1024, T=512, H=512, D_IN=D_OUT=32), fp32.
// Persistent kernel: 128 CTAs x 256 threads, software grid barrier.
// Decoder feedback GEMM folded into precomputed M = dec_Wih0 @ out_W.
// ---------------------------------------------------------------------------

#define NB   128          // CTAs (<= 148 SMs -> all co-resident)
#define NT   256
#define B_    64
#define H_    512
#define G4    2048
#define DIN   32
#define DOUT  32
#define SLEN  1024
#define TLEN  512
#define SH_STRIDE 132     // 128 + 4 pad: conflict-free, 16B aligned

struct P {
    const float *src;
    const float *eWih0, *eWhh0, *ebih0, *ebhh0;
    const float *eWih1, *eWhh1, *ebih1, *ebhh1;
    const float *dWih0, *dWhh0, *dbih0, *dbhh0;
    const float *dWih1, *dWhh1, *dbih1, *dbhh1;
    const float *outW, *outB;
    float *out;
};

// ---- persistent state (device globals; allocation-free scratch) ----
__device__ float gH0[2][B_ * H_];
__device__ float gH1[2][B_ * H_];
__device__ float gC0[B_ * H_];
__device__ float gC1[B_ * H_];
__device__ float gM[G4 * H_];      // dec_Wih0 @ out_W   [2048 x 512]
__device__ float gB2[G4];          // dec_Wih0 @ out_b
__device__ unsigned g_count = 0;
__device__ volatile unsigned g_gen = 0;

__device__ __forceinline__ void grid_bar() {
    __threadfence();
    __syncthreads();
    if (threadIdx.x == 0) {
        unsigned gen = g_gen;
        unsigned t = atomicAdd(&g_count, 1u);
        if (t == (unsigned)(NB - 1)) {
            atomicExch(&g_count, 0u);
            __threadfence();
            g_gen = gen + 1u;
        } else {
            while (g_gen == gen) { __nanosleep(64); }
        }
    }
    __syncthreads();
}

__device__ __forceinline__ float sigm(float x) { return 1.0f / (1.0f + expf(-x)); }

// Accumulate gates += x @ W.T restricted to this thread's (gate,unit) row r.
// x: [64 x K] with row stride ld; W: [2048 x K] row-major.
// cg=true -> x is mutable cross-CTA state (bypass L1 with .cg).
__device__ __forceinline__ void accum_term(
    const float* __restrict__ x, int ld,
    const float* __restrict__ W, int K, bool cg,
    int r, int bhalf, int bq, float acc[4], float* sh)
{
    const int tid = threadIdx.x;
    for (int k0 = 0; k0 < K; k0 += 128) {
        const int kc  = (K - k0 < 128) ? (K - k0) : 128;
        const int kcq = kc >> 2;                       // float4 per row (32 or 8)
        const int lsh = (kcq == 32) ? 5 : 3;
        const int nf4 = kcq << 6;                      // 64 * kcq
        for (int idx = tid; idx < nf4; idx += NT) {
            int b  = idx >> lsh;
            int kq = idx & (kcq - 1);
            const float4* gp = (const float4*)(x + b * ld + k0) + kq;
            float4 v = cg ? __ldcg(gp) : __ldg(gp);
            *(float4*)(sh + b * SH_STRIDE + (kq << 2)) = v;
        }
        __syncthreads();
        const float* wr = W + (long)r * K + k0;
        const float* hb = sh + ((bhalf << 5) + bq) * SH_STRIDE;
        for (int kk = 0; kk < kc; kk += 4) {
            float4 wv = __ldg((const float4*)(wr + kk));
            #pragma unroll
            for (int m = 0; m < 4; m++) {
                float4 hv = *(const float4*)(hb + m * (8 * SH_STRIDE) + kk);
                acc[m] = fmaf(wv.x, hv.x,
                         fmaf(wv.y, hv.y,
                         fmaf(wv.z, hv.z,
                         fmaf(wv.w, hv.w, acc[m]))));
            }
        }
        __syncthreads();
    }
}

// One LSTM layer step: gates = xA@WA.T + xB@WB.T + bih + bhh (+ b2);
// c,h updated in place / to hout. CTA covers units [4*blockIdx, 4*blockIdx+4).
__device__ __forceinline__ void lstm_phase(
    const float* xA, int ldA, const float* WA, int KA, bool cgA,
    const float* xB, int ldB, const float* WB, int KB, bool cgB,
    const float* __restrict__ bih, const float* __restrict__ bhh,
    const float* __restrict__ b2,
    float* __restrict__ cstate, float* __restrict__ hout, float* sh)
{
    const int tid   = threadIdx.x;
    const int warp  = tid >> 5, lane = tid & 31;
    const int bhalf = warp >> 2, uloc = warp & 3;
    const int gate  = lane & 3,  bq   = lane >> 2;
    const int u = (blockIdx.x << 2) + uloc;
    const int r = (gate << 9) + u;             // gate*512 + unit  (i,f,g,o order)

    float base = __ldg(bih + r) + __ldg(bhh + r);
    if (b2) base += __ldg(b2 + r);
    float acc[4] = {base, base, base, base};

    if (KA) accum_term(xA, ldA, WA, KA, cgA, r, bhalf, bq, acc, sh);
    if (KB) accum_term(xB, ldB, WB, KB, cgB, r, bhalf, bq, acc, sh);

    const int srcbase = lane & ~3;
    #pragma unroll
    for (int m = 0; m < 4; m++) {
        float gi = __shfl_sync(0xffffffffu, acc[m], srcbase + 0);
        float gf = __shfl_sync(0xffffffffu, acc[m], srcbase + 1);
        float gg = __shfl_sync(0xffffffffu, acc[m], srcbase + 2);
        float go = __shfl_sync(0xffffffffu, acc[m], srcbase + 3);
        if (gate == 0) {
            int b   = (bhalf << 5) + bq + (m << 3);
            int idx = (b << 9) + u;
            float cp = __ldcg(cstate + idx);
            float cn = sigm(gf) * cp + sigm(gi) * tanhf(gg);
            __stcg(cstate + idx, cn);
            __stcg(hout + idx, sigm(go) * tanhf(cn));
        }
    }
}

// pred(t) = h1 @ out_W.T + out_b -> d_out[:, t, :]. CTAs 0..31 only.
__device__ __forceinline__ void do_pred(const P& p, const float* __restrict__ h1, int t)
{
    int g = blockIdx.x * NT + threadIdx.x;     // 0..8191
    int oid = g >> 2, part = g & 3;            // 2048 outputs, K split by 4
    int b = oid >> 5, j = oid & 31;
    const float* hr = h1 + (b << 9) + (part << 7);
    const float* wr = p.outW + (j << 9) + (part << 7);
    float s = 0.0f;
    #pragma unroll
    for (int k = 0; k < 128; k += 4) {
        float4 hv = __ldcg((const float4*)(hr + k));
        float4 wv = __ldg ((const float4*)(wr + k));
        s = fmaf(hv.x, wv.x, fmaf(hv.y, wv.y, fmaf(hv.z, wv.z, fmaf(hv.w, wv.w, s))));
    }
    s += __shfl_xor_sync(0xffffffffu, s, 1);
    s += __shfl_xor_sync(0xffffffffu, s, 2);
    if (part == 0)
        p.out[((long)b << 14) + (t << 5) + j] = s + __ldg(p.outB + j);
}

__global__ void __launch_bounds__(NT, 1) seq2seq_kernel(P p)
{
    __shared__ float sh[B_ * SH_STRIDE];
    const int gt = blockIdx.x * NT + threadIdx.x;   // 0..32767 (== 64*512)

    // ---- zero init of states (every run; d_out poisoned by harness) ----
    __stcg(&gH0[0][gt], 0.0f);
    __stcg(&gH1[0][gt], 0.0f);
    __stcg(&gC0[gt],    0.0f);
    __stcg(&gC1[gt],    0.0f);
    grid_bar();

    // ---- precompute M = dec_Wih0 @ out_W, b2 = dec_Wih0 @ out_b ----
    for (int o = gt; o < G4 * H_; o += NB * NT) {
        int rr = o >> 9, hc = o & 511;
        const float* wr = p.dWih0 + rr * DIN;
        const float* oc = p.outW + hc;
        float s = 0.0f;
        #pragma unroll
        for (int j = 0; j < DIN; j++) s = fmaf(__ldg(wr + j), __ldg(oc + j * H_), s);
        __stcg(&gM[o], s);
    }
    if (gt < G4) {
        const float* wr = p.dWih0 + gt * DIN;
        float s = 0.0f;
        #pragma unroll
        for (int j = 0; j < DIN; j++) s = fmaf(__ldg(wr + j), __ldg(p.outB + j), s);
        __stcg(&gB2[gt], s);
    }
    grid_bar();

    // ---- encoder: 1024 steps x 2 layers ----
    for (int t = 0; t < SLEN; t++) {
        const int rp = t & 1, wp = 1 - rp;
        lstm_phase(p.src + t * DIN, SLEN * DIN, p.eWih0, DIN, false,
                   gH0[rp], H_, p.eWhh0, H_, true,
                   p.ebih0, p.ebhh0, nullptr, gC0, gH0[wp], sh);
        grid_bar();
        lstm_phase(gH0[wp], H_, p.eWih1, H_, true,
                   gH1[rp], H_, p.eWhh1, H_, true,
                   p.ebih1, p.ebhh1, nullptr, gC1, gH1[wp], sh);
        grid_bar();
    }

    // ---- decoder: 512 steps x 2 layers (+ pred side job) ----
    // gates_L0(t) = h1(t-1)@M.T + h0(t-1)@dWhh0.T + bias + b2   (t>0)
    for (int t = 0; t < TLEN; t++) {
        const int rp = t & 1, wp = 1 - rp;   // S even -> parity continues
        lstm_phase(t ? gH1[rp] : nullptr, H_, gM, t ? H_ : 0, true,
                   gH0[rp], H_, p.dWhh0, H_, true,
                   p.dbih0, p.dbhh0, t ? gB2 : nullptr, gC0, gH0[wp], sh);
        if (t > 0 && blockIdx.x < 32) do_pred(p, gH1[rp], t - 1);
        grid_bar();
        lstm_phase(gH0[wp], H_, p.dWih1, H_, true,
                   gH1[rp], H_, p.dWhh1, H_, true,
                   p.dbih1, p.dbhh1, nullptr, gC1, gH1[wp], sh);
        grid_bar();
    }
    // final pred for t = TLEN-1 (h1 ended in buffer parity TLEN&1 == 0)
    if (blockIdx.x < 32) do_pred(p, gH1[0], TLEN - 1);
}

extern "C" void kernel_launch(void* const* d_in, const int* in_sizes, int n_in,
                              void* d_out, int out_size)
{
    // target_length may or may not be passed as a size-1 scalar at index 1.
    const int o = (in_sizes[1] < 100) ? 1 : 0;   // enc_Wih0 has 65536 elems

    P p;
    p.src   = (const float*)d_in[0];
    p.eWih0 = (const float*)d_in[1 + o];
    p.eWhh0 = (const float*)d_in[2 + o];
    p.ebih0 = (const float*)d_in[3 + o];
    p.ebhh0 = (const float*)d_in[4 + o];
    p.eWih1 = (const float*)d_in[5 + o];
    p.eWhh1 = (const float*)d_in[6 + o];
    p.ebih1 = (const float*)d_in[7 + o];
    p.ebhh1 = (const float*)d_in[8 + o];
    p.dWih0 = (const float*)d_in[9 + o];
    p.dWhh0 = (const float*)d_in[10 + o];
    p.dbih0 = (const float*)d_in[11 + o];
    p.dbhh0 = (const float*)d_in[12 + o];
    p.dWih1 = (const float*)d_in[13 + o];
    p.dWhh1 = (const float*)d_in[14 + o];
    p.dbih1 = (const float*)d_in[15 + o];
    p.dbhh1 = (const float*)d_in[16 + o];
    p.outW  = (const float*)d_in[17 + o];
    p.outB  = (const float*)d_in[18 + o];
    p.out   = (float*)d_out;

    seq2seq_kernel<<<NB, NT>>>(p);
}